// round 13
// baseline (speedup 1.0000x reference)
#include <cuda_runtime.h>
#include <cuda_bf16.h>
#include <mma.h>
#include <cstdint>
#include <math.h>

using namespace nvcuda;

#define N_NODES 100000
#define N_EDGES 600000
#define D 128
#define NGRAPH 64
#define NUM_LAYER 3
#define NBLK 391                 // scan blocks per relation (ceil(100000/256))

// ---------------- scratch (static device globals; no allocation) ----------------
__device__ float g_bufA[(size_t)N_NODES * D];
__device__ float g_bufB[(size_t)N_NODES * D];
// layer-0 agg buffers: bf16 hi/lo planes [plane(2)][N_NODES][64] uint32 per rel
__device__ __align__(16) float g_in0[(size_t)N_NODES * D];
__device__ __align__(16) float g_in1[(size_t)N_NODES * D];
__device__ int   g_gstart[NGRAPH + 1];
// CSR scratch (2 relations)
__device__ int g_rowptr[2][N_NODES + 1];   // hist (degrees at +1)
__device__ int g_rowS[2][N_NODES];         // global row start
__device__ int g_deg[2][N_NODES];          // degree
__device__ int g_cursor[2][N_NODES];       // fill cursors
__device__ int g_csrsrc[2][N_EDGES];
__device__ int g_ctr[2];                   // scan base counters
// pre-split weight planes: per (layer,rel): [W1h, W1l, W2h, W2l]
__device__ __align__(16) __nv_bfloat16 g_wplanes[(size_t)NUM_LAYER * 2 * 4 * D * D];

// split fp32 pair into bf16 hi plane + bf16 residual plane (packed bf16x2)
__device__ __forceinline__ void split2(float a, float b, uint32_t& hi, uint32_t& lo) {
    __nv_bfloat16 ha = __float2bfloat16(a), hb = __float2bfloat16(b);
    float ra = a - __bfloat162float(ha);
    float rb = b - __bfloat162float(hb);
    __nv_bfloat162 H; H.x = ha; H.y = hb;
    __nv_bfloat162 L; L.x = __float2bfloat16(ra); L.y = __float2bfloat16(rb);
    hi = *(uint32_t*)&H;
    lo = *(uint32_t*)&L;
}

__device__ __forceinline__ void cp_async16(uint32_t smem_addr, const void* gptr) {
    asm volatile("cp.async.ca.shared.global [%0], [%1], 16;"
                 :: "r"(smem_addr), "l"(gptr));
}
#define CP_COMMIT() asm volatile("cp.async.commit_group;" ::: "memory")
#define CP_WAIT0()  asm volatile("cp.async.wait_group 0;" ::: "memory")

// ---------------- combo: edge histogram (both rels) + weight pre-split -----------
#define HIST_BLKS ((2 * N_EDGES + 255) / 256)             // 4688
#define WSPLIT_ITEMS (NUM_LAYER * 2 * (D * D / 2))        // 49152
#define WSPLIT_BLKS ((WSPLIT_ITEMS + 255) / 256)          // 192
__global__ void combo_kernel(const int* __restrict__ e_pos,
                             const int* __restrict__ e_inv,
                             const float* __restrict__ l1w,
                             const float* __restrict__ l2w,
                             __nv_bfloat16* __restrict__ wp,
                             int* __restrict__ rowptr /*[2][N+1]*/) {
    int bid = blockIdx.x;
    if (bid < HIST_BLKS) {
        int e = bid * 256 + threadIdx.x;
        if (e >= 2 * N_EDGES) return;
        int rel = e >= N_EDGES;
        const int* ei = rel ? e_inv : e_pos;
        int le = e - rel * N_EDGES;
        int dst = ei[N_EDGES + le];
        atomicAdd(&rowptr[(size_t)rel * (N_NODES + 1) + dst + 1], 1);
    } else {
        int i = (bid - HIST_BLKS) * 256 + threadIdx.x;
        if (i == 0) { g_ctr[0] = 0; g_ctr[1] = 0; }
        if (i >= WSPLIT_ITEMS) return;
        int mat = i / (D * D / 2);
        int p = i % (D * D / 2);
        float2 a = ((const float2*)l1w)[i];
        float2 b = ((const float2*)l2w)[i];
        uint32_t h, l;
        size_t base = (size_t)mat * 4 * D * D;
        split2(a.x, a.y, h, l);
        ((uint32_t*)&wp[base + 0 * D * D])[p] = h;
        ((uint32_t*)&wp[base + 1 * D * D])[p] = l;
        split2(b.x, b.y, h, l);
        ((uint32_t*)&wp[base + 2 * D * D])[p] = h;
        ((uint32_t*)&wp[base + 3 * D * D])[p] = l;
    }
}

// ---- single-pass scan: block-local scan + atomic global base --------------------
__global__ void scan1_kernel(const int* __restrict__ rowptr,
                             int* __restrict__ rowS, int* __restrict__ deg,
                             int* __restrict__ cursor) {
    __shared__ int s[256];
    __shared__ int base_sh;
    int rel = blockIdx.x >= NBLK;
    int b = blockIdx.x - rel * NBLK;
    const int* rp = rowptr + (size_t)rel * (N_NODES + 1);
    int idx = b * 256 + threadIdx.x;
    int v = (idx < N_NODES) ? rp[idx + 1] : 0;
    s[threadIdx.x] = v;
    __syncthreads();
#pragma unroll
    for (int o = 1; o < 256; o <<= 1) {
        int t = (threadIdx.x >= o) ? s[threadIdx.x - o] : 0;
        __syncthreads();
        s[threadIdx.x] += t;
        __syncthreads();
    }
    if (threadIdx.x == 255) base_sh = atomicAdd(&g_ctr[rel], s[255]);
    __syncthreads();
    if (idx < N_NODES) {
        int start = base_sh + s[threadIdx.x] - v;
        size_t o = (size_t)rel * N_NODES + idx;
        rowS[o] = start;
        cursor[o] = start;
        deg[o] = v;
    }
}

// ---------------- fill CSR (both rels) -------------------------------------------
__global__ void fill_kernel(const int* __restrict__ e_pos,
                            const int* __restrict__ e_inv,
                            int* __restrict__ cursor,
                            int* __restrict__ csrsrc) {
    int e = blockIdx.x * 256 + threadIdx.x;
    if (e >= 2 * N_EDGES) return;
    int rel = e >= N_EDGES;
    const int* ei = rel ? e_inv : e_pos;
    int le = e - rel * N_EDGES;
    int src = ei[le];
    int dst = ei[N_EDGES + le];
    int pos = atomicAdd(&cursor[(size_t)rel * N_NODES + dst], 1);
    csrsrc[(size_t)rel * N_EDGES + pos] = src;
}

// write fp32 accumulator (float4 at lane) as bf16 hi/lo planes
__device__ __forceinline__ void store_agg_planes(uint32_t* aggP, int node, int lane,
                                                 float4 acc) {
    uint32_t h0, l0, h1, l1;
    split2(acc.x, acc.y, h0, l0);
    split2(acc.z, acc.w, h1, l1);
    ((uint2*)(aggP + (size_t)node * 64))[lane] = make_uint2(h0, h1);
    ((uint2*)(aggP + (size_t)N_NODES * 64 + (size_t)node * 64))[lane] = make_uint2(l0, l1);
}

// ---- layer-0: fused embedding + dual gather (combined 28-entry table) -----------
__global__ void embed_gather2_kernel(const int* __restrict__ x,
                                     const float* __restrict__ type_emb,
                                     const float* __restrict__ output_emb,
                                     const int* __restrict__ rowS,
                                     const int* __restrict__ deg,
                                     const int* __restrict__ csrsrc,
                                     uint32_t* __restrict__ aggP0,
                                     uint32_t* __restrict__ aggP1) {
    __shared__ float sc[28 * D];   // c[o*14+t] = type_emb[t] + output_emb[o]
    for (int i = threadIdx.x; i < 28 * (D / 4); i += 256) {
        int vec = i >> 5, c = i & 31;
        int t = vec % 14, o = vec / 14;
        float4 a = ((const float4*)(type_emb + (size_t)t * D))[c];
        float4 b = ((const float4*)(output_emb + (size_t)o * D))[c];
        ((float4*)(sc + (size_t)vec * D))[c] =
            make_float4(a.x + b.x, a.y + b.y, a.z + b.z, a.w + b.w);
    }
    __syncthreads();

    int warp = (blockIdx.x * blockDim.x + threadIdx.x) >> 5;
    int lane = threadIdx.x & 31;
    if (warp >= N_NODES) return;

    int2 xn = ((const int2*)x)[warp];
    float4 base = ((const float4*)(sc + (size_t)(xn.y * 14 + xn.x) * D))[lane];
#pragma unroll
    for (int rel = 0; rel < 2; rel++) {
        const int* cs = csrsrc + (size_t)rel * N_EDGES;
        size_t o = (size_t)rel * N_NODES + warp;
        int s = rowS[o], e = s + deg[o];
        float4 acc = base;
        for (int i = s; i < e; i++) {
            int src = __ldg(&cs[i]);
            int2 xs = ((const int2*)x)[src];
            float4 v = ((const float4*)(sc + (size_t)(xs.y * 14 + xs.x) * D))[lane];
            acc.x += v.x; acc.y += v.y; acc.z += v.z; acc.w += v.w;
        }
        store_agg_planes(rel ? aggP1 : aggP0, warp, lane, acc);
    }
}

// ---------------- smem layout (bytes) -------------------------------------------
#define SSTRIDE 136
#define A_PLANE  (64 * SSTRIDE * 2)      // 17408
#define W_PLANE  (128 * SSTRIDE * 2)     // 34816
#define SM_B1      0
#define SM_B2S     1024
#define SM_SCRATCH 1536
#define SM_AH      (SM_SCRATCH + 8192)   // 9728 (16B aligned)
#define SM_AL      (SM_AH + A_PLANE)
#define SM_WH      (SM_AL + A_PLANE)
#define SM_WL      (SM_WH + W_PLANE)
#define SM_TOTAL   (SM_WL + W_PLANE)     // 114176 -> 2 CTAs/SM

typedef wmma::fragment<wmma::matrix_a, 16, 16, 16, __nv_bfloat16, wmma::row_major> AFrag;
typedef wmma::fragment<wmma::matrix_b, 16, 16, 16, __nv_bfloat16, wmma::row_major> BFrag;
typedef wmma::fragment<wmma::accumulator, 16, 16, 16, float> CFrag;

// ==== merged dual-relation GIN layer (M=64 tile, 2 CTAs/SM) =====================
// use_gather=0: A tiles staged from pre-split planes (aggP0/1) via cp.async
// use_gather=1: A tiles gathered in-kernel from fp32 h via CSR (warp per 8 rows)
// Relation processing order alternates by SM-pair parity so co-resident CTAs are
// anti-phased (one gathers while the other runs MMAs).
__global__ void __launch_bounds__(256, 2)
gin_dual_kernel(const uint32_t* __restrict__ aggP0, const uint32_t* __restrict__ aggP1,
                const float* __restrict__ h,
                const int* __restrict__ rowS, const int* __restrict__ deg,
                const int* __restrict__ csrsrc,
                const __nv_bfloat16* __restrict__ wp,
                const float* __restrict__ b1, const float* __restrict__ b2,
                float* __restrict__ out, int relu_out, int use_gather) {
    extern __shared__ char sm[];
    float* b1s = (float*)(sm + SM_B1);
    float* b2s = (float*)(sm + SM_B2S);
    __nv_bfloat16* sAh = (__nv_bfloat16*)(sm + SM_AH);
    __nv_bfloat16* sAl = (__nv_bfloat16*)(sm + SM_AL);
    __nv_bfloat16* sWh = (__nv_bfloat16*)(sm + SM_WH);
    __nv_bfloat16* sWl = (__nv_bfloat16*)(sm + SM_WL);
    const uint32_t sbase = (uint32_t)__cvta_generic_to_shared(sm);

    const int tid = threadIdx.x;
    const int wid = tid >> 5;
    const int lane = tid & 31;
    const int row0 = blockIdx.x * 64;
    const int rel_first = (blockIdx.x / 148) & 1;   // anti-phase co-resident CTAs

    if (tid < 128) {
        b1s[tid]       = b1[tid];
        b1s[128 + tid] = b1[128 + tid];
        b2s[tid]       = b2[tid] + b2[128 + tid];
    }

    const int mwarp = wid >> 2;        // 0..1
    const int nwarp = wid & 3;         // 0..3
    const int m0 = mwarp * 32;
    const int n0w = nwarp * 32;
    float* sw = (float*)(sm + SM_SCRATCH) + wid * 256;
    const int r = lane >> 1, half = lane & 1;

    CFrag accT[2][2];
#pragma unroll
    for (int mt = 0; mt < 2; mt++)
#pragma unroll
        for (int nt = 0; nt < 2; nt++) wmma::fill_fragment(accT[mt][nt], 0.f);

#pragma unroll
    for (int ri = 0; ri < 2; ri++) {
        const int rel = ri ^ rel_first;
        const __nv_bfloat16* wpr = wp + (size_t)rel * 4 * D * D;
        if (ri == 1) __syncthreads();   // prev rel's smem reads complete

        // ---- stage W1 planes via cp.async ----
        {
            const __nv_bfloat16* whp = wpr;
            const __nv_bfloat16* wlp = wpr + D * D;
            for (int i = tid; i < 128 * 16 * 2; i += 256) {
                int plane = i >= 128 * 16;
                int j = i & (128 * 16 - 1);
                int k = j >> 4, c = j & 15;
                uint32_t dst = sbase + (plane ? SM_WL : SM_WH) + (k * SSTRIDE + c * 8) * 2;
                cp_async16(dst, (plane ? wlp : whp) + k * D + c * 8);
            }
        }
        // ---- A tile ----
        if (use_gather) {
            // warp-gather: warp wid owns rows [wid*8, wid*8+8)
            const int* cs = csrsrc + (size_t)rel * N_EDGES;
            const int* rS = rowS + (size_t)rel * N_NODES;
            const int* dG = deg + (size_t)rel * N_NODES;
#pragma unroll 2
            for (int j = 0; j < 8; j++) {
                int m = wid * 8 + j;
                int row = row0 + m;
                float4 acc = make_float4(0.f, 0.f, 0.f, 0.f);
                if (row < N_NODES) {
                    acc = ((const float4*)(h + (size_t)row * D))[lane];
                    int s = __ldg(&rS[row]), e = s + __ldg(&dG[row]);
                    for (int i = s; i < e; i++) {
                        int src = __ldg(&cs[i]);
                        float4 v = ((const float4*)(h + (size_t)src * D))[lane];
                        acc.x += v.x; acc.y += v.y; acc.z += v.z; acc.w += v.w;
                    }
                }
                uint32_t hi, lo;
                split2(acc.x, acc.y, hi, lo);
                *(uint32_t*)&sAh[m * SSTRIDE + 4 * lane] = hi;
                *(uint32_t*)&sAl[m * SSTRIDE + 4 * lane] = lo;
                split2(acc.z, acc.w, hi, lo);
                *(uint32_t*)&sAh[m * SSTRIDE + 4 * lane + 2] = hi;
                *(uint32_t*)&sAl[m * SSTRIDE + 4 * lane + 2] = lo;
            }
            CP_COMMIT();     // W1 group
        } else {
            const uint32_t* aggP = (rel == 0) ? aggP0 : aggP1;
            for (int i = tid; i < 64 * 16 * 2; i += 256) {
                int plane = i >= 64 * 16;
                int j = i & (64 * 16 - 1);
                int m = j >> 4, c = j & 15;
                int row = row0 + m;
                uint32_t off = (plane ? SM_AL : SM_AH) + (m * SSTRIDE + c * 8) * 2;
                if (row < N_NODES) {
                    cp_async16(sbase + off,
                               aggP + (size_t)plane * N_NODES * 64 + (size_t)row * 64 + c * 4);
                } else {
                    *(uint4*)(sm + off) = make_uint4(0, 0, 0, 0);
                }
            }
            CP_COMMIT();
        }
        CP_WAIT0();
        __syncthreads();

        // ------- GEMM1: accW = A @ W1 (3 split terms) -------
        CFrag accW[2][2];
#pragma unroll
        for (int mt = 0; mt < 2; mt++)
#pragma unroll
            for (int nt = 0; nt < 2; nt++) wmma::fill_fragment(accW[mt][nt], 0.f);

        for (int k = 0; k < 128; k += 16) {
            AFrag ah[2], al[2];
#pragma unroll
            for (int mt = 0; mt < 2; mt++) {
                wmma::load_matrix_sync(ah[mt], sAh + (m0 + mt * 16) * SSTRIDE + k, SSTRIDE);
                wmma::load_matrix_sync(al[mt], sAl + (m0 + mt * 16) * SSTRIDE + k, SSTRIDE);
            }
#pragma unroll
            for (int nt = 0; nt < 2; nt++) {
                BFrag bh, bl;
                wmma::load_matrix_sync(bh, sWh + k * SSTRIDE + n0w + nt * 16, SSTRIDE);
                wmma::load_matrix_sync(bl, sWl + k * SSTRIDE + n0w + nt * 16, SSTRIDE);
#pragma unroll
                for (int mt = 0; mt < 2; mt++) {
                    wmma::mma_sync(accW[mt][nt], ah[mt], bh, accW[mt][nt]);
                    wmma::mma_sync(accW[mt][nt], ah[mt], bl, accW[mt][nt]);
                    wmma::mma_sync(accW[mt][nt], al[mt], bh, accW[mt][nt]);
                }
            }
        }
        __syncthreads();   // W1/A reads complete

        // ------- prefetch W2 via cp.async, overlapped with epilogue1 -------
        {
            const __nv_bfloat16* whp = wpr + 2 * D * D;
            const __nv_bfloat16* wlp = wpr + 3 * D * D;
            for (int i = tid; i < 128 * 16 * 2; i += 256) {
                int plane = i >= 128 * 16;
                int j = i & (128 * 16 - 1);
                int k = j >> 4, c = j & 15;
                uint32_t dst = sbase + (plane ? SM_WL : SM_WH) + (k * SSTRIDE + c * 8) * 2;
                cp_async16(dst, (plane ? wlp : whp) + k * D + c * 8);
            }
            CP_COMMIT();
        }

        // ------- epilogue1: z = relu(accW + b1[rel]) -> A planes -------
        const float* b1r = b1s + rel * 128;
#pragma unroll
        for (int mt = 0; mt < 2; mt++) {
#pragma unroll
            for (int nt = 0; nt < 2; nt++) {
                wmma::store_matrix_sync(sw, accW[mt][nt], 16, wmma::mem_row_major);
                __syncwarp();
#pragma unroll
                for (int q = 0; q < 4; q++) {
                    int c0 = half * 8 + 2 * q;
                    int n0 = n0w + nt * 16 + c0;
                    float z0 = fmaxf(sw[r * 16 + c0]     + b1r[n0],     0.f);
                    float z1 = fmaxf(sw[r * 16 + c0 + 1] + b1r[n0 + 1], 0.f);
                    uint32_t hi, lo;
                    split2(z0, z1, hi, lo);
                    int mrow = m0 + mt * 16 + r;
                    *(uint32_t*)&sAh[mrow * SSTRIDE + n0] = hi;
                    *(uint32_t*)&sAl[mrow * SSTRIDE + n0] = lo;
                }
                __syncwarp();
            }
        }
        CP_WAIT0();
        __syncthreads();   // z + W2 visible

        // ------- GEMM2: accT += Z @ W2 (3 split terms) -------
        for (int k = 0; k < 128; k += 16) {
            AFrag ah[2], al[2];
#pragma unroll
            for (int mt = 0; mt < 2; mt++) {
                wmma::load_matrix_sync(ah[mt], sAh + (m0 + mt * 16) * SSTRIDE + k, SSTRIDE);
                wmma::load_matrix_sync(al[mt], sAl + (m0 + mt * 16) * SSTRIDE + k, SSTRIDE);
            }
#pragma unroll
            for (int nt = 0; nt < 2; nt++) {
                BFrag bh, bl;
                wmma::load_matrix_sync(bh, sWh + k * SSTRIDE + n0w + nt * 16, SSTRIDE);
                wmma::load_matrix_sync(bl, sWl + k * SSTRIDE + n0w + nt * 16, SSTRIDE);
#pragma unroll
                for (int mt = 0; mt < 2; mt++) {
                    wmma::mma_sync(accT[mt][nt], ah[mt], bh, accT[mt][nt]);
                    wmma::mma_sync(accT[mt][nt], ah[mt], bl, accT[mt][nt]);
                    wmma::mma_sync(accT[mt][nt], al[mt], bh, accT[mt][nt]);
                }
            }
        }
    }

    // ---- final epilogue: out = maybe_relu(accT + b2_0 + b2_1) ----
#pragma unroll
    for (int mt = 0; mt < 2; mt++) {
        const int row = row0 + m0 + mt * 16 + r;
#pragma unroll
        for (int nt = 0; nt < 2; nt++) {
            wmma::store_matrix_sync(sw, accT[mt][nt], 16, wmma::mem_row_major);
            __syncwarp();
            if (row < N_NODES) {
                int n0 = n0w + nt * 16 + half * 8;
                float* op = out + (size_t)row * D + n0;
                float v[8];
#pragma unroll
                for (int j = 0; j < 8; j++) v[j] = sw[r * 16 + half * 8 + j] + b2s[n0 + j];
                if (relu_out) {
#pragma unroll
                    for (int j = 0; j < 8; j++) v[j] = fmaxf(v[j], 0.f);
                }
                *(float4*)(op)     = make_float4(v[0], v[1], v[2], v[3]);
                *(float4*)(op + 4) = make_float4(v[4], v[5], v[6], v[7]);
            }
            __syncwarp();
        }
    }
}

// ---------------- graph segment boundaries ---------------------------------------
__global__ void bounds_kernel(const int* __restrict__ batch) {
    int g = threadIdx.x;
    if (g > NGRAPH) return;
    int lo = 0, hi = N_NODES;
    while (lo < hi) {
        int mid = (lo + hi) >> 1;
        if (batch[mid] < g) lo = mid + 1; else hi = mid;
    }
    g_gstart[g] = lo;
}

// ---------------- pooling --------------------------------------------------------
__global__ void pool_kernel(const float* __restrict__ h, float* __restrict__ out,
                            int out_size) {
    int b = blockIdx.x;
    int c = threadIdx.x;
    int s = g_gstart[b], e = g_gstart[b + 1];
    float s0 = 0.f, s1 = 0.f, s2 = 0.f, s3 = 0.f;
    float mx = -INFINITY, mn = INFINITY;
    int r = s;
    for (; r + 4 <= e; r += 4) {
        float v0 = h[(size_t)(r + 0) * D + c];
        float v1 = h[(size_t)(r + 1) * D + c];
        float v2 = h[(size_t)(r + 2) * D + c];
        float v3 = h[(size_t)(r + 3) * D + c];
        s0 += v0; s1 += v1; s2 += v2; s3 += v3;
        mx = fmaxf(mx, fmaxf(fmaxf(v0, v1), fmaxf(v2, v3)));
        mn = fminf(mn, fminf(fminf(v0, v1), fminf(v2, v3)));
    }
    for (; r < e; r++) {
        float v = h[(size_t)r * D + c];
        s0 += v; mx = fmaxf(mx, v); mn = fminf(mn, v);
    }
    float sum = (s0 + s1) + (s2 + s3);
    float cnt = (float)(e - s);
    float mean = sum / fmaxf(cnt, 1.f);
    float vals[4] = { sum, mean, mx, mn };
#pragma unroll
    for (int a = 0; a < 4; a++) {
        int m = a * D + c;
        out[b * 512 + (m & 3) * 128 + (m >> 2)] = vals[a];
    }
    if (c < 4) {
        int idx = NGRAPH * 4 * D + b * 4 + c;
        if (idx < out_size) out[idx] = 1.0f;
    }
}

// ---------------- launch ---------------------------------------------------------
extern "C" void kernel_launch(void* const* d_in, const int* in_sizes, int n_in,
                              void* d_out, int out_size) {
    const int*   x          = (const int*)d_in[0];
    const int*   e_pos      = (const int*)d_in[1];
    const int*   e_inv      = (const int*)d_in[2];
    const int*   batch      = (const int*)d_in[3];
    const float* type_emb   = (const float*)d_in[4];
    const float* output_emb = (const float*)d_in[5];
    const float* l1w        = (const float*)d_in[6];
    const float* l1b        = (const float*)d_in[7];
    const float* l2w        = (const float*)d_in[8];
    const float* l2b        = (const float*)d_in[9];
    float* out = (float*)d_out;

    float *hA, *hB;
    uint32_t *i0, *i1;
    int *rowptr, *rowS, *deg, *cursor, *csrsrc;
    __nv_bfloat16* wp;
    cudaGetSymbolAddress((void**)&hA, g_bufA);
    cudaGetSymbolAddress((void**)&hB, g_bufB);
    cudaGetSymbolAddress((void**)&i0, g_in0);
    cudaGetSymbolAddress((void**)&i1, g_in1);
    cudaGetSymbolAddress((void**)&rowptr, g_rowptr);
    cudaGetSymbolAddress((void**)&rowS, g_rowS);
    cudaGetSymbolAddress((void**)&deg, g_deg);
    cudaGetSymbolAddress((void**)&cursor, g_cursor);
    cudaGetSymbolAddress((void**)&csrsrc, g_csrsrc);
    cudaGetSymbolAddress((void**)&wp, g_wplanes);

    cudaFuncSetAttribute(gin_dual_kernel,
                         cudaFuncAttributeMaxDynamicSharedMemorySize, SM_TOTAL);

    cudaMemsetAsync(rowptr, 0, 2 * (N_NODES + 1) * sizeof(int));

    // ---- CSR build + weight pre-split ----
    combo_kernel<<<HIST_BLKS + WSPLIT_BLKS, 256>>>(e_pos, e_inv, l1w, l2w, wp, rowptr);
    scan1_kernel<<<2 * NBLK, 256>>>(rowptr, rowS, deg, cursor);
    fill_kernel<<<(2 * N_EDGES + 255) / 256, 256>>>(e_pos, e_inv, cursor, csrsrc);

    const int gemm_grid = (N_NODES + 63) / 64;     // 1563
    const int gather_grid = (N_NODES * 32 + 255) / 256;

    // layer-0 aggregation in embedding space -> bf16 planes
    embed_gather2_kernel<<<gather_grid, 256>>>(x, type_emb, output_emb,
                                               rowS, deg, csrsrc, i0, i1);

    float* h  = hA;
    float* hn = hB;
    for (int l = 0; l < NUM_LAYER; l++) {
        const __nv_bfloat16* wpl = wp + (size_t)l * 2 * 4 * D * D;
        const float* b1p = l1b + (size_t)l * 2 * D;
        const float* b2p = l2b + (size_t)l * 2 * D;
        gin_dual_kernel<<<gemm_grid, 256, SM_TOTAL>>>(
            i0, i1, h, rowS, deg, csrsrc, wpl, b1p, b2p, hn,
            /*relu_out=*/(l < NUM_LAYER - 1) ? 1 : 0,
            /*use_gather=*/(l > 0) ? 1 : 0);
        float* tmp = h; h = hn; hn = tmp;
    }

    bounds_kernel<<<1, NGRAPH + 1>>>(batch);
    pool_kernel<<<NGRAPH, D>>>(h, out, out_size);
}

// round 14
// speedup vs baseline: 1.0353x; 1.0353x over previous
#include <cuda_runtime.h>
#include <cuda_bf16.h>
#include <mma.h>
#include <cstdint>
#include <math.h>

using namespace nvcuda;

#define N_NODES 100000
#define N_EDGES 600000
#define D 128
#define NGRAPH 64
#define NUM_LAYER 3
#define NBLK 391                 // scan blocks per relation (ceil(100000/256))

// ---------------- scratch (static device globals; no allocation) ----------------
__device__ float g_bufA[(size_t)N_NODES * D];
__device__ float g_bufB[(size_t)N_NODES * D];
// agg buffers: bf16 hi/lo planes [plane(2)][N_NODES][64] uint32 per rel
__device__ __align__(16) float g_in0[(size_t)N_NODES * D];
__device__ __align__(16) float g_in1[(size_t)N_NODES * D];
// CSR scratch (2 relations)
__device__ int g_rowptr[2][N_NODES + 1];   // hist (degrees at +1)
__device__ int g_rowS[2][N_NODES];         // global row start
__device__ int g_deg[2][N_NODES];          // degree
__device__ int g_cursor[2][N_NODES];       // fill cursors
__device__ int g_csrsrc[2][N_EDGES];
__device__ int g_ctr[2];                   // scan base counters
// pre-split weight planes: per (layer,rel): [W1h, W1l, W2h, W2l]
__device__ __align__(16) __nv_bfloat16 g_wplanes[(size_t)NUM_LAYER * 2 * 4 * D * D];

// split fp32 pair into bf16 hi plane + bf16 residual plane (packed bf16x2)
__device__ __forceinline__ void split2(float a, float b, uint32_t& hi, uint32_t& lo) {
    __nv_bfloat16 ha = __float2bfloat16(a), hb = __float2bfloat16(b);
    float ra = a - __bfloat162float(ha);
    float rb = b - __bfloat162float(hb);
    __nv_bfloat162 H; H.x = ha; H.y = hb;
    __nv_bfloat162 L; L.x = __float2bfloat16(ra); L.y = __float2bfloat16(rb);
    hi = *(uint32_t*)&H;
    lo = *(uint32_t*)&L;
}

__device__ __forceinline__ void cp_async16(uint32_t smem_addr, const void* gptr) {
    asm volatile("cp.async.ca.shared.global [%0], [%1], 16;"
                 :: "r"(smem_addr), "l"(gptr));
}
#define CP_COMMIT() asm volatile("cp.async.commit_group;" ::: "memory")
#define CP_WAIT0()  asm volatile("cp.async.wait_group 0;" ::: "memory")

// ---------------- combo: edge histogram (both rels) + weight pre-split -----------
#define HIST_BLKS ((2 * N_EDGES + 255) / 256)             // 4688
#define WSPLIT_ITEMS (NUM_LAYER * 2 * (D * D / 2))        // 49152
#define WSPLIT_BLKS ((WSPLIT_ITEMS + 255) / 256)          // 192
__global__ void combo_kernel(const int* __restrict__ e_pos,
                             const int* __restrict__ e_inv,
                             const float* __restrict__ l1w,
                             const float* __restrict__ l2w,
                             __nv_bfloat16* __restrict__ wp,
                             int* __restrict__ rowptr /*[2][N+1]*/) {
    int bid = blockIdx.x;
    if (bid < HIST_BLKS) {
        int e = bid * 256 + threadIdx.x;
        if (e >= 2 * N_EDGES) return;
        int rel = e >= N_EDGES;
        const int* ei = rel ? e_inv : e_pos;
        int le = e - rel * N_EDGES;
        int dst = ei[N_EDGES + le];
        atomicAdd(&rowptr[(size_t)rel * (N_NODES + 1) + dst + 1], 1);
    } else {
        int i = (bid - HIST_BLKS) * 256 + threadIdx.x;
        if (i == 0) { g_ctr[0] = 0; g_ctr[1] = 0; }
        if (i >= WSPLIT_ITEMS) return;
        int mat = i / (D * D / 2);
        int p = i % (D * D / 2);
        float2 a = ((const float2*)l1w)[i];
        float2 b = ((const float2*)l2w)[i];
        uint32_t h, l;
        size_t base = (size_t)mat * 4 * D * D;
        split2(a.x, a.y, h, l);
        ((uint32_t*)&wp[base + 0 * D * D])[p] = h;
        ((uint32_t*)&wp[base + 1 * D * D])[p] = l;
        split2(b.x, b.y, h, l);
        ((uint32_t*)&wp[base + 2 * D * D])[p] = h;
        ((uint32_t*)&wp[base + 3 * D * D])[p] = l;
    }
}

// ---- single-pass scan: block-local scan + atomic global base --------------------
__global__ void scan1_kernel(const int* __restrict__ rowptr,
                             int* __restrict__ rowS, int* __restrict__ deg,
                             int* __restrict__ cursor) {
    __shared__ int s[256];
    __shared__ int base_sh;
    int rel = blockIdx.x >= NBLK;
    int b = blockIdx.x - rel * NBLK;
    const int* rp = rowptr + (size_t)rel * (N_NODES + 1);
    int idx = b * 256 + threadIdx.x;
    int v = (idx < N_NODES) ? rp[idx + 1] : 0;
    s[threadIdx.x] = v;
    __syncthreads();
#pragma unroll
    for (int o = 1; o < 256; o <<= 1) {
        int t = (threadIdx.x >= o) ? s[threadIdx.x - o] : 0;
        __syncthreads();
        s[threadIdx.x] += t;
        __syncthreads();
    }
    if (threadIdx.x == 255) base_sh = atomicAdd(&g_ctr[rel], s[255]);
    __syncthreads();
    if (idx < N_NODES) {
        int start = base_sh + s[threadIdx.x] - v;
        size_t o = (size_t)rel * N_NODES + idx;
        rowS[o] = start;
        cursor[o] = start;
        deg[o] = v;
    }
}

// ---------------- fill CSR (both rels) -------------------------------------------
__global__ void fill_kernel(const int* __restrict__ e_pos,
                            const int* __restrict__ e_inv,
                            int* __restrict__ cursor,
                            int* __restrict__ csrsrc) {
    int e = blockIdx.x * 256 + threadIdx.x;
    if (e >= 2 * N_EDGES) return;
    int rel = e >= N_EDGES;
    const int* ei = rel ? e_inv : e_pos;
    int le = e - rel * N_EDGES;
    int src = ei[le];
    int dst = ei[N_EDGES + le];
    int pos = atomicAdd(&cursor[(size_t)rel * N_NODES + dst], 1);
    csrsrc[(size_t)rel * N_EDGES + pos] = src;
}

// write fp32 accumulator (float4 at lane) as bf16 hi/lo planes
__device__ __forceinline__ void store_agg_planes(uint32_t* aggP, int node, int lane,
                                                 float4 acc) {
    uint32_t h0, l0, h1, l1;
    split2(acc.x, acc.y, h0, l0);
    split2(acc.z, acc.w, h1, l1);
    ((uint2*)(aggP + (size_t)node * 64))[lane] = make_uint2(h0, h1);
    ((uint2*)(aggP + (size_t)N_NODES * 64 + (size_t)node * 64))[lane] = make_uint2(l0, l1);
}

// ---- layer-0: fused embedding + dual gather (combined 28-entry table) -----------
__global__ void embed_gather2_kernel(const int* __restrict__ x,
                                     const float* __restrict__ type_emb,
                                     const float* __restrict__ output_emb,
                                     const int* __restrict__ rowS,
                                     const int* __restrict__ deg,
                                     const int* __restrict__ csrsrc,
                                     uint32_t* __restrict__ aggP0,
                                     uint32_t* __restrict__ aggP1) {
    __shared__ float sc[28 * D];   // c[o*14+t] = type_emb[t] + output_emb[o]
    for (int i = threadIdx.x; i < 28 * (D / 4); i += 256) {
        int vec = i >> 5, c = i & 31;
        int t = vec % 14, o = vec / 14;
        float4 a = ((const float4*)(type_emb + (size_t)t * D))[c];
        float4 b = ((const float4*)(output_emb + (size_t)o * D))[c];
        ((float4*)(sc + (size_t)vec * D))[c] =
            make_float4(a.x + b.x, a.y + b.y, a.z + b.z, a.w + b.w);
    }
    __syncthreads();

    int warp = (blockIdx.x * blockDim.x + threadIdx.x) >> 5;
    int lane = threadIdx.x & 31;
    if (warp >= N_NODES) return;

    int2 xn = ((const int2*)x)[warp];
    float4 base = ((const float4*)(sc + (size_t)(xn.y * 14 + xn.x) * D))[lane];
#pragma unroll
    for (int rel = 0; rel < 2; rel++) {
        const int* cs = csrsrc + (size_t)rel * N_EDGES;
        size_t o = (size_t)rel * N_NODES + warp;
        int s = rowS[o], e = s + deg[o];
        float4 acc = base;
        for (int i = s; i < e; i++) {
            int src = __ldg(&cs[i]);
            int2 xs = ((const int2*)x)[src];
            float4 v = ((const float4*)(sc + (size_t)(xs.y * 14 + xs.x) * D))[lane];
            acc.x += v.x; acc.y += v.y; acc.z += v.z; acc.w += v.w;
        }
        store_agg_planes(rel ? aggP1 : aggP0, warp, lane, acc);
    }
}

// ---- layers 1+: dual gather from fp32 h -> bf16 planes --------------------------
__global__ void gather2_kernel(const float* __restrict__ h,
                               const int* __restrict__ rowS,
                               const int* __restrict__ deg,
                               const int* __restrict__ csrsrc,
                               uint32_t* __restrict__ aggP0,
                               uint32_t* __restrict__ aggP1) {
    int warp = (blockIdx.x * blockDim.x + threadIdx.x) >> 5;
    int lane = threadIdx.x & 31;
    if (warp >= N_NODES) return;
    float4 base = ((const float4*)(h + (size_t)warp * D))[lane];
#pragma unroll
    for (int rel = 0; rel < 2; rel++) {
        const int* cs = csrsrc + (size_t)rel * N_EDGES;
        size_t o = (size_t)rel * N_NODES + warp;
        int s = rowS[o], e = s + deg[o];
        float4 acc = base;
        for (int i = s; i < e; i++) {
            int src = __ldg(&cs[i]);
            float4 v = ((const float4*)(h + (size_t)src * D))[lane];
            acc.x += v.x; acc.y += v.y; acc.z += v.z; acc.w += v.w;
        }
        store_agg_planes(rel ? aggP1 : aggP0, warp, lane, acc);
    }
}

// ---------------- smem layout (bytes) -------------------------------------------
#define SSTRIDE 136
#define A_PLANE  (64 * SSTRIDE * 2)      // 17408
#define W_PLANE  (128 * SSTRIDE * 2)     // 34816
#define SM_B1      0
#define SM_B2S     1024
#define SM_SCRATCH 1536
#define SM_AH      (SM_SCRATCH + 8192)   // 9728 (16B aligned)
#define SM_AL      (SM_AH + A_PLANE)
#define SM_WH      (SM_AL + A_PLANE)
#define SM_WL      (SM_WH + W_PLANE)
#define SM_TOTAL   (SM_WL + W_PLANE)     // 114176 -> 2 CTAs/SM

typedef wmma::fragment<wmma::matrix_a, 16, 16, 16, __nv_bfloat16, wmma::row_major> AFrag;
typedef wmma::fragment<wmma::matrix_b, 16, 16, 16, __nv_bfloat16, wmma::row_major> BFrag;
typedef wmma::fragment<wmma::accumulator, 16, 16, 16, float> CFrag;

// ==== merged dual-relation GIN layer (M=64 tile, 2 CTAs/SM, cp.async staged) ====
__global__ void __launch_bounds__(256, 2)
gin_dual_kernel(const uint32_t* __restrict__ aggP0, const uint32_t* __restrict__ aggP1,
                const __nv_bfloat16* __restrict__ wp,
                const float* __restrict__ b1, const float* __restrict__ b2,
                float* __restrict__ out, int relu_out) {
    extern __shared__ char sm[];
    float* b1s = (float*)(sm + SM_B1);
    float* b2s = (float*)(sm + SM_B2S);
    __nv_bfloat16* sAh = (__nv_bfloat16*)(sm + SM_AH);
    __nv_bfloat16* sAl = (__nv_bfloat16*)(sm + SM_AL);
    __nv_bfloat16* sWh = (__nv_bfloat16*)(sm + SM_WH);
    __nv_bfloat16* sWl = (__nv_bfloat16*)(sm + SM_WL);
    const uint32_t sbase = (uint32_t)__cvta_generic_to_shared(sm);

    const int tid = threadIdx.x;
    const int wid = tid >> 5;
    const int lane = tid & 31;
    const int row0 = blockIdx.x * 64;

    if (tid < 128) {
        b1s[tid]       = b1[tid];
        b1s[128 + tid] = b1[128 + tid];
        b2s[tid]       = b2[tid] + b2[128 + tid];
    }

    const int mwarp = wid >> 2;        // 0..1
    const int nwarp = wid & 3;         // 0..3
    const int m0 = mwarp * 32;
    const int n0w = nwarp * 32;
    float* sw = (float*)(sm + SM_SCRATCH) + wid * 256;
    const int r = lane >> 1, half = lane & 1;

    CFrag accT[2][2];
#pragma unroll
    for (int mt = 0; mt < 2; mt++)
#pragma unroll
        for (int nt = 0; nt < 2; nt++) wmma::fill_fragment(accT[mt][nt], 0.f);

#pragma unroll
    for (int rel = 0; rel < 2; rel++) {
        const uint32_t* aggP = (rel == 0) ? aggP0 : aggP1;
        const __nv_bfloat16* wpr = wp + (size_t)rel * 4 * D * D;
        if (rel == 1) __syncthreads();   // prev rel's smem reads complete

        // ---- stage W1 planes via cp.async ----
        {
            const __nv_bfloat16* whp = wpr;
            const __nv_bfloat16* wlp = wpr + D * D;
            for (int i = tid; i < 128 * 16 * 2; i += 256) {
                int plane = i >= 128 * 16;
                int j = i & (128 * 16 - 1);
                int k = j >> 4, c = j & 15;
                uint32_t dst = sbase + (plane ? SM_WL : SM_WH) + (k * SSTRIDE + c * 8) * 2;
                cp_async16(dst, (plane ? wlp : whp) + k * D + c * 8);
            }
        }
        // ---- stage A planes via cp.async (pre-split bf16 hi/lo in gmem) ----
        for (int i = tid; i < 64 * 16 * 2; i += 256) {
            int plane = i >= 64 * 16;
            int j = i & (64 * 16 - 1);
            int m = j >> 4, c = j & 15;
            int row = row0 + m;
            uint32_t off = (plane ? SM_AL : SM_AH) + (m * SSTRIDE + c * 8) * 2;
            if (row < N_NODES) {
                cp_async16(sbase + off,
                           aggP + (size_t)plane * N_NODES * 64 + (size_t)row * 64 + c * 4);
            } else {
                *(uint4*)(sm + off) = make_uint4(0, 0, 0, 0);
            }
        }
        CP_COMMIT();
        CP_WAIT0();
        __syncthreads();

        // ------- GEMM1: accW = A @ W1 (3 split terms) -------
        CFrag accW[2][2];
#pragma unroll
        for (int mt = 0; mt < 2; mt++)
#pragma unroll
            for (int nt = 0; nt < 2; nt++) wmma::fill_fragment(accW[mt][nt], 0.f);

        for (int k = 0; k < 128; k += 16) {
            AFrag ah[2], al[2];
#pragma unroll
            for (int mt = 0; mt < 2; mt++) {
                wmma::load_matrix_sync(ah[mt], sAh + (m0 + mt * 16) * SSTRIDE + k, SSTRIDE);
                wmma::load_matrix_sync(al[mt], sAl + (m0 + mt * 16) * SSTRIDE + k, SSTRIDE);
            }
#pragma unroll
            for (int nt = 0; nt < 2; nt++) {
                BFrag bh, bl;
                wmma::load_matrix_sync(bh, sWh + k * SSTRIDE + n0w + nt * 16, SSTRIDE);
                wmma::load_matrix_sync(bl, sWl + k * SSTRIDE + n0w + nt * 16, SSTRIDE);
#pragma unroll
                for (int mt = 0; mt < 2; mt++) {
                    wmma::mma_sync(accW[mt][nt], ah[mt], bh, accW[mt][nt]);
                    wmma::mma_sync(accW[mt][nt], ah[mt], bl, accW[mt][nt]);
                    wmma::mma_sync(accW[mt][nt], al[mt], bh, accW[mt][nt]);
                }
            }
        }
        __syncthreads();   // W1/A reads complete

        // ------- prefetch W2 via cp.async, overlapped with epilogue1 -------
        {
            const __nv_bfloat16* whp = wpr + 2 * D * D;
            const __nv_bfloat16* wlp = wpr + 3 * D * D;
            for (int i = tid; i < 128 * 16 * 2; i += 256) {
                int plane = i >= 128 * 16;
                int j = i & (128 * 16 - 1);
                int k = j >> 4, c = j & 15;
                uint32_t dst = sbase + (plane ? SM_WL : SM_WH) + (k * SSTRIDE + c * 8) * 2;
                cp_async16(dst, (plane ? wlp : whp) + k * D + c * 8);
            }
            CP_COMMIT();
        }

        // ------- epilogue1: z = relu(accW + b1[rel]) -> A planes -------
        const float* b1r = b1s + rel * 128;
#pragma unroll
        for (int mt = 0; mt < 2; mt++) {
#pragma unroll
            for (int nt = 0; nt < 2; nt++) {
                wmma::store_matrix_sync(sw, accW[mt][nt], 16, wmma::mem_row_major);
                __syncwarp();
#pragma unroll
                for (int q = 0; q < 4; q++) {
                    int c0 = half * 8 + 2 * q;
                    int n0 = n0w + nt * 16 + c0;
                    float z0 = fmaxf(sw[r * 16 + c0]     + b1r[n0],     0.f);
                    float z1 = fmaxf(sw[r * 16 + c0 + 1] + b1r[n0 + 1], 0.f);
                    uint32_t hi, lo;
                    split2(z0, z1, hi, lo);
                    int mrow = m0 + mt * 16 + r;
                    *(uint32_t*)&sAh[mrow * SSTRIDE + n0] = hi;
                    *(uint32_t*)&sAl[mrow * SSTRIDE + n0] = lo;
                }
                __syncwarp();
            }
        }
        CP_WAIT0();
        __syncthreads();   // z + W2 visible

        // ------- GEMM2: accT += Z @ W2 (3 split terms) -------
        for (int k = 0; k < 128; k += 16) {
            AFrag ah[2], al[2];
#pragma unroll
            for (int mt = 0; mt < 2; mt++) {
                wmma::load_matrix_sync(ah[mt], sAh + (m0 + mt * 16) * SSTRIDE + k, SSTRIDE);
                wmma::load_matrix_sync(al[mt], sAl + (m0 + mt * 16) * SSTRIDE + k, SSTRIDE);
            }
#pragma unroll
            for (int nt = 0; nt < 2; nt++) {
                BFrag bh, bl;
                wmma::load_matrix_sync(bh, sWh + k * SSTRIDE + n0w + nt * 16, SSTRIDE);
                wmma::load_matrix_sync(bl, sWl + k * SSTRIDE + n0w + nt * 16, SSTRIDE);
#pragma unroll
                for (int mt = 0; mt < 2; mt++) {
                    wmma::mma_sync(accT[mt][nt], ah[mt], bh, accT[mt][nt]);
                    wmma::mma_sync(accT[mt][nt], ah[mt], bl, accT[mt][nt]);
                    wmma::mma_sync(accT[mt][nt], al[mt], bh, accT[mt][nt]);
                }
            }
        }
    }

    // ---- final epilogue: out = maybe_relu(accT + b2_0 + b2_1) ----
#pragma unroll
    for (int mt = 0; mt < 2; mt++) {
        const int row = row0 + m0 + mt * 16 + r;
#pragma unroll
        for (int nt = 0; nt < 2; nt++) {
            wmma::store_matrix_sync(sw, accT[mt][nt], 16, wmma::mem_row_major);
            __syncwarp();
            if (row < N_NODES) {
                int n0 = n0w + nt * 16 + half * 8;
                float* op = out + (size_t)row * D + n0;
                float v[8];
#pragma unroll
                for (int j = 0; j < 8; j++) v[j] = sw[r * 16 + half * 8 + j] + b2s[n0 + j];
                if (relu_out) {
#pragma unroll
                    for (int j = 0; j < 8; j++) v[j] = fmaxf(v[j], 0.f);
                }
                *(float4*)(op)     = make_float4(v[0], v[1], v[2], v[3]);
                *(float4*)(op + 4) = make_float4(v[4], v[5], v[6], v[7]);
            }
            __syncwarp();
        }
    }
}

// ---------------- pooling (inline graph-bounds binary search) --------------------
__global__ void pool_kernel(const float* __restrict__ h,
                            const int* __restrict__ batch,
                            float* __restrict__ out, int out_size) {
    int b = blockIdx.x;
    int c = threadIdx.x;
    // bounds via binary search on sorted batch (broadcast loads, all lanes same addr)
    int s, e;
    {
        int lo = 0, hi = N_NODES;
        while (lo < hi) { int mid = (lo + hi) >> 1; if (batch[mid] < b) lo = mid + 1; else hi = mid; }
        s = lo;
        lo = 0; hi = N_NODES;
        while (lo < hi) { int mid = (lo + hi) >> 1; if (batch[mid] < b + 1) lo = mid + 1; else hi = mid; }
        e = lo;
    }
    float s0 = 0.f, s1 = 0.f, s2 = 0.f, s3 = 0.f;
    float mx = -INFINITY, mn = INFINITY;
    int r = s;
    for (; r + 4 <= e; r += 4) {
        float v0 = h[(size_t)(r + 0) * D + c];
        float v1 = h[(size_t)(r + 1) * D + c];
        float v2 = h[(size_t)(r + 2) * D + c];
        float v3 = h[(size_t)(r + 3) * D + c];
        s0 += v0; s1 += v1; s2 += v2; s3 += v3;
        mx = fmaxf(mx, fmaxf(fmaxf(v0, v1), fmaxf(v2, v3)));
        mn = fminf(mn, fminf(fminf(v0, v1), fminf(v2, v3)));
    }
    for (; r < e; r++) {
        float v = h[(size_t)r * D + c];
        s0 += v; mx = fmaxf(mx, v); mn = fminf(mn, v);
    }
    float sum = (s0 + s1) + (s2 + s3);
    float cnt = (float)(e - s);
    float mean = sum / fmaxf(cnt, 1.f);
    float vals[4] = { sum, mean, mx, mn };
#pragma unroll
    for (int a = 0; a < 4; a++) {
        int m = a * D + c;
        out[b * 512 + (m & 3) * 128 + (m >> 2)] = vals[a];
    }
    if (c < 4) {
        int idx = NGRAPH * 4 * D + b * 4 + c;
        if (idx < out_size) out[idx] = 1.0f;
    }
}

// ---------------- launch ---------------------------------------------------------
extern "C" void kernel_launch(void* const* d_in, const int* in_sizes, int n_in,
                              void* d_out, int out_size) {
    const int*   x          = (const int*)d_in[0];
    const int*   e_pos      = (const int*)d_in[1];
    const int*   e_inv      = (const int*)d_in[2];
    const int*   batch      = (const int*)d_in[3];
    const float* type_emb   = (const float*)d_in[4];
    const float* output_emb = (const float*)d_in[5];
    const float* l1w        = (const float*)d_in[6];
    const float* l1b        = (const float*)d_in[7];
    const float* l2w        = (const float*)d_in[8];
    const float* l2b        = (const float*)d_in[9];
    float* out = (float*)d_out;

    float *hA, *hB;
    uint32_t *i0, *i1;
    int *rowptr, *rowS, *deg, *cursor, *csrsrc;
    __nv_bfloat16* wp;
    cudaGetSymbolAddress((void**)&hA, g_bufA);
    cudaGetSymbolAddress((void**)&hB, g_bufB);
    cudaGetSymbolAddress((void**)&i0, g_in0);
    cudaGetSymbolAddress((void**)&i1, g_in1);
    cudaGetSymbolAddress((void**)&rowptr, g_rowptr);
    cudaGetSymbolAddress((void**)&rowS, g_rowS);
    cudaGetSymbolAddress((void**)&deg, g_deg);
    cudaGetSymbolAddress((void**)&cursor, g_cursor);
    cudaGetSymbolAddress((void**)&csrsrc, g_csrsrc);
    cudaGetSymbolAddress((void**)&wp, g_wplanes);

    cudaFuncSetAttribute(gin_dual_kernel,
                         cudaFuncAttributeMaxDynamicSharedMemorySize, SM_TOTAL);

    cudaMemsetAsync(rowptr, 0, 2 * (N_NODES + 1) * sizeof(int));

    // ---- CSR build + weight pre-split ----
    combo_kernel<<<HIST_BLKS + WSPLIT_BLKS, 256>>>(e_pos, e_inv, l1w, l2w, wp, rowptr);
    scan1_kernel<<<2 * NBLK, 256>>>(rowptr, rowS, deg, cursor);
    fill_kernel<<<(2 * N_EDGES + 255) / 256, 256>>>(e_pos, e_inv, cursor, csrsrc);

    const int gemm_grid = (N_NODES + 63) / 64;     // 1563
    const int gather_grid = (N_NODES * 32 + 255) / 256;

    // layer-0 aggregation in embedding space -> bf16 planes
    embed_gather2_kernel<<<gather_grid, 256>>>(x, type_emb, output_emb,
                                               rowS, deg, csrsrc, i0, i1);

    float* h  = hA;
    float* hn = hB;
    for (int l = 0; l < NUM_LAYER; l++) {
        if (l > 0)
            gather2_kernel<<<gather_grid, 256>>>(h, rowS, deg, csrsrc, i0, i1);

        const __nv_bfloat16* wpl = wp + (size_t)l * 2 * 4 * D * D;
        const float* b1p = l1b + (size_t)l * 2 * D;
        const float* b2p = l2b + (size_t)l * 2 * D;
        gin_dual_kernel<<<gemm_grid, 256, SM_TOTAL>>>(
            i0, i1, wpl, b1p, b2p, hn,
            /*relu_out=*/(l < NUM_LAYER - 1) ? 1 : 0);

        float* tmp = h; h = hn; hn = tmp;
    }

    pool_kernel<<<NGRAPH, D>>>(h, batch, out, out_size);
}

// round 15
// speedup vs baseline: 1.0765x; 1.0398x over previous
#include <cuda_runtime.h>
#include <cuda_bf16.h>
#include <mma.h>
#include <cstdint>
#include <math.h>

using namespace nvcuda;

#define N_NODES 100000
#define N_EDGES 600000
#define D 128
#define NGRAPH 64
#define NUM_LAYER 3
#define NBLK 391                 // scan blocks per relation (ceil(100000/256))

// ---------------- scratch (static device globals; no allocation) ----------------
__device__ float g_bufA[(size_t)N_NODES * D];
__device__ float g_bufB[(size_t)N_NODES * D];
// agg buffers: bf16 hi/lo planes [plane(2)][N_NODES][64] uint32 per rel
__device__ __align__(16) float g_in0[(size_t)N_NODES * D];
__device__ __align__(16) float g_in1[(size_t)N_NODES * D];
// CSR scratch (2 relations). g_rowptr starts zeroed (static init) and is
// re-zeroed at the END of every execution (in pool_kernel), so each graph
// replay sees the same initial state. No memset node needed.
__device__ int g_rowptr[2][N_NODES + 1];   // hist (degrees at +1)
__device__ int g_rowS[2][N_NODES];         // global row start
__device__ int g_deg[2][N_NODES];          // degree
__device__ int g_cursor[2][N_NODES];       // fill cursors
__device__ int g_csrsrc[2][N_EDGES];
__device__ int g_ctr[2];                   // scan base counters (zeroed in combo)
// pre-split weight planes: per (layer,rel): [W1h, W1l, W2h, W2l]
__device__ __align__(16) __nv_bfloat16 g_wplanes[(size_t)NUM_LAYER * 2 * 4 * D * D];

// split fp32 pair into bf16 hi plane + bf16 residual plane (packed bf16x2)
__device__ __forceinline__ void split2(float a, float b, uint32_t& hi, uint32_t& lo) {
    __nv_bfloat16 ha = __float2bfloat16(a), hb = __float2bfloat16(b);
    float ra = a - __bfloat162float(ha);
    float rb = b - __bfloat162float(hb);
    __nv_bfloat162 H; H.x = ha; H.y = hb;
    __nv_bfloat162 L; L.x = __float2bfloat16(ra); L.y = __float2bfloat16(rb);
    hi = *(uint32_t*)&H;
    lo = *(uint32_t*)&L;
}

__device__ __forceinline__ void cp_async16(uint32_t smem_addr, const void* gptr) {
    asm volatile("cp.async.ca.shared.global [%0], [%1], 16;"
                 :: "r"(smem_addr), "l"(gptr));
}
#define CP_COMMIT() asm volatile("cp.async.commit_group;" ::: "memory")
#define CP_WAIT0()  asm volatile("cp.async.wait_group 0;" ::: "memory")

// ---------------- combo: edge histogram (both rels) + weight pre-split -----------
#define HIST_BLKS ((2 * N_EDGES + 255) / 256)             // 4688
#define WSPLIT_ITEMS (NUM_LAYER * 2 * (D * D / 2))        // 49152
#define WSPLIT_BLKS ((WSPLIT_ITEMS + 255) / 256)          // 192
__global__ void combo_kernel(const int* __restrict__ e_pos,
                             const int* __restrict__ e_inv,
                             const float* __restrict__ l1w,
                             const float* __restrict__ l2w,
                             __nv_bfloat16* __restrict__ wp,
                             int* __restrict__ rowptr /*[2][N+1]*/) {
    int bid = blockIdx.x;
    if (bid < HIST_BLKS) {
        int e = bid * 256 + threadIdx.x;
        if (e >= 2 * N_EDGES) return;
        int rel = e >= N_EDGES;
        const int* ei = rel ? e_inv : e_pos;
        int le = e - rel * N_EDGES;
        int dst = ei[N_EDGES + le];
        atomicAdd(&rowptr[(size_t)rel * (N_NODES + 1) + dst + 1], 1);
    } else {
        int i = (bid - HIST_BLKS) * 256 + threadIdx.x;
        if (i == 0) { g_ctr[0] = 0; g_ctr[1] = 0; }
        if (i >= WSPLIT_ITEMS) return;
        int mat = i / (D * D / 2);
        int p = i % (D * D / 2);
        float2 a = ((const float2*)l1w)[i];
        float2 b = ((const float2*)l2w)[i];
        uint32_t h, l;
        size_t base = (size_t)mat * 4 * D * D;
        split2(a.x, a.y, h, l);
        ((uint32_t*)&wp[base + 0 * D * D])[p] = h;
        ((uint32_t*)&wp[base + 1 * D * D])[p] = l;
        split2(b.x, b.y, h, l);
        ((uint32_t*)&wp[base + 2 * D * D])[p] = h;
        ((uint32_t*)&wp[base + 3 * D * D])[p] = l;
    }
}

// ---- single-pass scan: block-local scan + atomic global base --------------------
__global__ void scan1_kernel(const int* __restrict__ rowptr,
                             int* __restrict__ rowS, int* __restrict__ deg,
                             int* __restrict__ cursor) {
    __shared__ int s[256];
    __shared__ int base_sh;
    int rel = blockIdx.x >= NBLK;
    int b = blockIdx.x - rel * NBLK;
    const int* rp = rowptr + (size_t)rel * (N_NODES + 1);
    int idx = b * 256 + threadIdx.x;
    int v = (idx < N_NODES) ? rp[idx + 1] : 0;
    s[threadIdx.x] = v;
    __syncthreads();
#pragma unroll
    for (int o = 1; o < 256; o <<= 1) {
        int t = (threadIdx.x >= o) ? s[threadIdx.x - o] : 0;
        __syncthreads();
        s[threadIdx.x] += t;
        __syncthreads();
    }
    if (threadIdx.x == 255) base_sh = atomicAdd(&g_ctr[rel], s[255]);
    __syncthreads();
    if (idx < N_NODES) {
        int start = base_sh + s[threadIdx.x] - v;
        size_t o = (size_t)rel * N_NODES + idx;
        rowS[o] = start;
        cursor[o] = start;
        deg[o] = v;
    }
}

// ---------------- fill CSR (both rels) -------------------------------------------
__global__ void fill_kernel(const int* __restrict__ e_pos,
                            const int* __restrict__ e_inv,
                            int* __restrict__ cursor,
                            int* __restrict__ csrsrc) {
    int e = blockIdx.x * 256 + threadIdx.x;
    if (e >= 2 * N_EDGES) return;
    int rel = e >= N_EDGES;
    const int* ei = rel ? e_inv : e_pos;
    int le = e - rel * N_EDGES;
    int src = ei[le];
    int dst = ei[N_EDGES + le];
    int pos = atomicAdd(&cursor[(size_t)rel * N_NODES + dst], 1);
    csrsrc[(size_t)rel * N_EDGES + pos] = src;
}

// write fp32 accumulator (float4 at lane) as bf16 hi/lo planes
__device__ __forceinline__ void store_agg_planes(uint32_t* aggP, int node, int lane,
                                                 float4 acc) {
    uint32_t h0, l0, h1, l1;
    split2(acc.x, acc.y, h0, l0);
    split2(acc.z, acc.w, h1, l1);
    ((uint2*)(aggP + (size_t)node * 64))[lane] = make_uint2(h0, h1);
    ((uint2*)(aggP + (size_t)N_NODES * 64 + (size_t)node * 64))[lane] = make_uint2(l0, l1);
}

// ---- layer-0: fused embedding + dual gather (combined 28-entry table) -----------
__global__ void embed_gather2_kernel(const int* __restrict__ x,
                                     const float* __restrict__ type_emb,
                                     const float* __restrict__ output_emb,
                                     const int* __restrict__ rowS,
                                     const int* __restrict__ deg,
                                     const int* __restrict__ csrsrc,
                                     uint32_t* __restrict__ aggP0,
                                     uint32_t* __restrict__ aggP1) {
    __shared__ float sc[28 * D];   // c[o*14+t] = type_emb[t] + output_emb[o]
    for (int i = threadIdx.x; i < 28 * (D / 4); i += 256) {
        int vec = i >> 5, c = i & 31;
        int t = vec % 14, o = vec / 14;
        float4 a = ((const float4*)(type_emb + (size_t)t * D))[c];
        float4 b = ((const float4*)(output_emb + (size_t)o * D))[c];
        ((float4*)(sc + (size_t)vec * D))[c] =
            make_float4(a.x + b.x, a.y + b.y, a.z + b.z, a.w + b.w);
    }
    __syncthreads();

    int warp = (blockIdx.x * blockDim.x + threadIdx.x) >> 5;
    int lane = threadIdx.x & 31;
    if (warp >= N_NODES) return;

    int2 xn = ((const int2*)x)[warp];
    float4 base = ((const float4*)(sc + (size_t)(xn.y * 14 + xn.x) * D))[lane];
#pragma unroll
    for (int rel = 0; rel < 2; rel++) {
        const int* cs = csrsrc + (size_t)rel * N_EDGES;
        size_t o = (size_t)rel * N_NODES + warp;
        int s = rowS[o], e = s + deg[o];
        float4 acc = base;
#pragma unroll 2
        for (int i = s; i < e; i++) {
            int src = __ldg(&cs[i]);
            int2 xs = ((const int2*)x)[src];
            float4 v = ((const float4*)(sc + (size_t)(xs.y * 14 + xs.x) * D))[lane];
            acc.x += v.x; acc.y += v.y; acc.z += v.z; acc.w += v.w;
        }
        store_agg_planes(rel ? aggP1 : aggP0, warp, lane, acc);
    }
}

// ---- layers 1+: dual gather from fp32 h -> bf16 planes --------------------------
__global__ void gather2_kernel(const float* __restrict__ h,
                               const int* __restrict__ rowS,
                               const int* __restrict__ deg,
                               const int* __restrict__ csrsrc,
                               uint32_t* __restrict__ aggP0,
                               uint32_t* __restrict__ aggP1) {
    int warp = (blockIdx.x * blockDim.x + threadIdx.x) >> 5;
    int lane = threadIdx.x & 31;
    if (warp >= N_NODES) return;
    float4 base = ((const float4*)(h + (size_t)warp * D))[lane];
#pragma unroll
    for (int rel = 0; rel < 2; rel++) {
        const int* cs = csrsrc + (size_t)rel * N_EDGES;
        size_t o = (size_t)rel * N_NODES + warp;
        int s = rowS[o], e = s + deg[o];
        float4 acc = base;
#pragma unroll 2
        for (int i = s; i < e; i++) {
            int src = __ldg(&cs[i]);
            float4 v = ((const float4*)(h + (size_t)src * D))[lane];
            acc.x += v.x; acc.y += v.y; acc.z += v.z; acc.w += v.w;
        }
        store_agg_planes(rel ? aggP1 : aggP0, warp, lane, acc);
    }
}

// ---------------- smem layout (bytes) -------------------------------------------
#define SSTRIDE 136
#define A_PLANE  (64 * SSTRIDE * 2)      // 17408
#define W_PLANE  (128 * SSTRIDE * 2)     // 34816
#define SM_B1      0
#define SM_B2S     1024
#define SM_SCRATCH 1536
#define SM_AH      (SM_SCRATCH + 8192)   // 9728 (16B aligned)
#define SM_AL      (SM_AH + A_PLANE)
#define SM_WH      (SM_AL + A_PLANE)
#define SM_WL      (SM_WH + W_PLANE)
#define SM_TOTAL   (SM_WL + W_PLANE)     // 114176 -> 2 CTAs/SM

typedef wmma::fragment<wmma::matrix_a, 16, 16, 16, __nv_bfloat16, wmma::row_major> AFrag;
typedef wmma::fragment<wmma::matrix_b, 16, 16, 16, __nv_bfloat16, wmma::row_major> BFrag;
typedef wmma::fragment<wmma::accumulator, 16, 16, 16, float> CFrag;

// ==== merged dual-relation GIN layer (M=64 tile, 2 CTAs/SM, cp.async staged) ====
__global__ void __launch_bounds__(256, 2)
gin_dual_kernel(const uint32_t* __restrict__ aggP0, const uint32_t* __restrict__ aggP1,
                const __nv_bfloat16* __restrict__ wp,
                const float* __restrict__ b1, const float* __restrict__ b2,
                float* __restrict__ out, int relu_out) {
    extern __shared__ char sm[];
    float* b1s = (float*)(sm + SM_B1);
    float* b2s = (float*)(sm + SM_B2S);
    __nv_bfloat16* sAh = (__nv_bfloat16*)(sm + SM_AH);
    __nv_bfloat16* sAl = (__nv_bfloat16*)(sm + SM_AL);
    __nv_bfloat16* sWh = (__nv_bfloat16*)(sm + SM_WH);
    __nv_bfloat16* sWl = (__nv_bfloat16*)(sm + SM_WL);
    const uint32_t sbase = (uint32_t)__cvta_generic_to_shared(sm);

    const int tid = threadIdx.x;
    const int wid = tid >> 5;
    const int lane = tid & 31;
    const int row0 = blockIdx.x * 64;

    if (tid < 128) {
        b1s[tid]       = b1[tid];
        b1s[128 + tid] = b1[128 + tid];
        b2s[tid]       = b2[tid] + b2[128 + tid];
    }

    const int mwarp = wid >> 2;        // 0..1
    const int nwarp = wid & 3;         // 0..3
    const int m0 = mwarp * 32;
    const int n0w = nwarp * 32;
    float* sw = (float*)(sm + SM_SCRATCH) + wid * 256;
    const int r = lane >> 1, half = lane & 1;

    CFrag accT[2][2];
#pragma unroll
    for (int mt = 0; mt < 2; mt++)
#pragma unroll
        for (int nt = 0; nt < 2; nt++) wmma::fill_fragment(accT[mt][nt], 0.f);

#pragma unroll
    for (int rel = 0; rel < 2; rel++) {
        const uint32_t* aggP = (rel == 0) ? aggP0 : aggP1;
        const __nv_bfloat16* wpr = wp + (size_t)rel * 4 * D * D;
        if (rel == 1) __syncthreads();   // prev rel's smem reads complete

        // ---- stage W1 planes via cp.async ----
        {
            const __nv_bfloat16* whp = wpr;
            const __nv_bfloat16* wlp = wpr + D * D;
            for (int i = tid; i < 128 * 16 * 2; i += 256) {
                int plane = i >= 128 * 16;
                int j = i & (128 * 16 - 1);
                int k = j >> 4, c = j & 15;
                uint32_t dst = sbase + (plane ? SM_WL : SM_WH) + (k * SSTRIDE + c * 8) * 2;
                cp_async16(dst, (plane ? wlp : whp) + k * D + c * 8);
            }
        }
        // ---- stage A planes via cp.async (pre-split bf16 hi/lo in gmem) ----
        for (int i = tid; i < 64 * 16 * 2; i += 256) {
            int plane = i >= 64 * 16;
            int j = i & (64 * 16 - 1);
            int m = j >> 4, c = j & 15;
            int row = row0 + m;
            uint32_t off = (plane ? SM_AL : SM_AH) + (m * SSTRIDE + c * 8) * 2;
            if (row < N_NODES) {
                cp_async16(sbase + off,
                           aggP + (size_t)plane * N_NODES * 64 + (size_t)row * 64 + c * 4);
            } else {
                *(uint4*)(sm + off) = make_uint4(0, 0, 0, 0);
            }
        }
        CP_COMMIT();
        CP_WAIT0();
        __syncthreads();

        // ------- GEMM1: accW = A @ W1 (3 split terms) -------
        CFrag accW[2][2];
#pragma unroll
        for (int mt = 0; mt < 2; mt++)
#pragma unroll
            for (int nt = 0; nt < 2; nt++) wmma::fill_fragment(accW[mt][nt], 0.f);

        for (int k = 0; k < 128; k += 16) {
            AFrag ah[2], al[2];
#pragma unroll
            for (int mt = 0; mt < 2; mt++) {
                wmma::load_matrix_sync(ah[mt], sAh + (m0 + mt * 16) * SSTRIDE + k, SSTRIDE);
                wmma::load_matrix_sync(al[mt], sAl + (m0 + mt * 16) * SSTRIDE + k, SSTRIDE);
            }
#pragma unroll
            for (int nt = 0; nt < 2; nt++) {
                BFrag bh, bl;
                wmma::load_matrix_sync(bh, sWh + k * SSTRIDE + n0w + nt * 16, SSTRIDE);
                wmma::load_matrix_sync(bl, sWl + k * SSTRIDE + n0w + nt * 16, SSTRIDE);
#pragma unroll
                for (int mt = 0; mt < 2; mt++) {
                    wmma::mma_sync(accW[mt][nt], ah[mt], bh, accW[mt][nt]);
                    wmma::mma_sync(accW[mt][nt], ah[mt], bl, accW[mt][nt]);
                    wmma::mma_sync(accW[mt][nt], al[mt], bh, accW[mt][nt]);
                }
            }
        }
        __syncthreads();   // W1/A reads complete

        // ------- prefetch W2 via cp.async, overlapped with epilogue1 -------
        {
            const __nv_bfloat16* whp = wpr + 2 * D * D;
            const __nv_bfloat16* wlp = wpr + 3 * D * D;
            for (int i = tid; i < 128 * 16 * 2; i += 256) {
                int plane = i >= 128 * 16;
                int j = i & (128 * 16 - 1);
                int k = j >> 4, c = j & 15;
                uint32_t dst = sbase + (plane ? SM_WL : SM_WH) + (k * SSTRIDE + c * 8) * 2;
                cp_async16(dst, (plane ? wlp : whp) + k * D + c * 8);
            }
            CP_COMMIT();
        }

        // ------- epilogue1: z = relu(accW + b1[rel]) -> A planes -------
        const float* b1r = b1s + rel * 128;
#pragma unroll
        for (int mt = 0; mt < 2; mt++) {
#pragma unroll
            for (int nt = 0; nt < 2; nt++) {
                wmma::store_matrix_sync(sw, accW[mt][nt], 16, wmma::mem_row_major);
                __syncwarp();
#pragma unroll
                for (int q = 0; q < 4; q++) {
                    int c0 = half * 8 + 2 * q;
                    int n0 = n0w + nt * 16 + c0;
                    float z0 = fmaxf(sw[r * 16 + c0]     + b1r[n0],     0.f);
                    float z1 = fmaxf(sw[r * 16 + c0 + 1] + b1r[n0 + 1], 0.f);
                    uint32_t hi, lo;
                    split2(z0, z1, hi, lo);
                    int mrow = m0 + mt * 16 + r;
                    *(uint32_t*)&sAh[mrow * SSTRIDE + n0] = hi;
                    *(uint32_t*)&sAl[mrow * SSTRIDE + n0] = lo;
                }
                __syncwarp();
            }
        }
        CP_WAIT0();
        __syncthreads();   // z + W2 visible

        // ------- GEMM2: accT += Z @ W2 (3 split terms) -------
        for (int k = 0; k < 128; k += 16) {
            AFrag ah[2], al[2];
#pragma unroll
            for (int mt = 0; mt < 2; mt++) {
                wmma::load_matrix_sync(ah[mt], sAh + (m0 + mt * 16) * SSTRIDE + k, SSTRIDE);
                wmma::load_matrix_sync(al[mt], sAl + (m0 + mt * 16) * SSTRIDE + k, SSTRIDE);
            }
#pragma unroll
            for (int nt = 0; nt < 2; nt++) {
                BFrag bh, bl;
                wmma::load_matrix_sync(bh, sWh + k * SSTRIDE + n0w + nt * 16, SSTRIDE);
                wmma::load_matrix_sync(bl, sWl + k * SSTRIDE + n0w + nt * 16, SSTRIDE);
#pragma unroll
                for (int mt = 0; mt < 2; mt++) {
                    wmma::mma_sync(accT[mt][nt], ah[mt], bh, accT[mt][nt]);
                    wmma::mma_sync(accT[mt][nt], ah[mt], bl, accT[mt][nt]);
                    wmma::mma_sync(accT[mt][nt], al[mt], bh, accT[mt][nt]);
                }
            }
        }
    }

    // ---- final epilogue: out = maybe_relu(accT + b2_0 + b2_1) ----
#pragma unroll
    for (int mt = 0; mt < 2; mt++) {
        const int row = row0 + m0 + mt * 16 + r;
#pragma unroll
        for (int nt = 0; nt < 2; nt++) {
            wmma::store_matrix_sync(sw, accT[mt][nt], 16, wmma::mem_row_major);
            __syncwarp();
            if (row < N_NODES) {
                int n0 = n0w + nt * 16 + half * 8;
                float* op = out + (size_t)row * D + n0;
                float v[8];
#pragma unroll
                for (int j = 0; j < 8; j++) v[j] = sw[r * 16 + half * 8 + j] + b2s[n0 + j];
                if (relu_out) {
#pragma unroll
                    for (int j = 0; j < 8; j++) v[j] = fmaxf(v[j], 0.f);
                }
                *(float4*)(op)     = make_float4(v[0], v[1], v[2], v[3]);
                *(float4*)(op + 4) = make_float4(v[4], v[5], v[6], v[7]);
            }
            __syncwarp();
        }
    }
}

// ---------------- pooling (inline bounds search) + rowptr cleanup ----------------
__global__ void pool_kernel(const float* __restrict__ h,
                            const int* __restrict__ batch,
                            float* __restrict__ out, int out_size) {
    int b = blockIdx.x;
    int c = threadIdx.x;
    int s, e;
    {
        int lo = 0, hi = N_NODES;
        while (lo < hi) { int mid = (lo + hi) >> 1; if (batch[mid] < b) lo = mid + 1; else hi = mid; }
        s = lo;
        lo = 0; hi = N_NODES;
        while (lo < hi) { int mid = (lo + hi) >> 1; if (batch[mid] < b + 1) lo = mid + 1; else hi = mid; }
        e = lo;
    }
    float s0 = 0.f, s1 = 0.f, s2 = 0.f, s3 = 0.f;
    float mx = -INFINITY, mn = INFINITY;
    int r = s;
    for (; r + 4 <= e; r += 4) {
        float v0 = h[(size_t)(r + 0) * D + c];
        float v1 = h[(size_t)(r + 1) * D + c];
        float v2 = h[(size_t)(r + 2) * D + c];
        float v3 = h[(size_t)(r + 3) * D + c];
        s0 += v0; s1 += v1; s2 += v2; s3 += v3;
        mx = fmaxf(mx, fmaxf(fmaxf(v0, v1), fmaxf(v2, v3)));
        mn = fminf(mn, fminf(fminf(v0, v1), fminf(v2, v3)));
    }
    for (; r < e; r++) {
        float v = h[(size_t)r * D + c];
        s0 += v; mx = fmaxf(mx, v); mn = fminf(mn, v);
    }
    float sum = (s0 + s1) + (s2 + s3);
    float cnt = (float)(e - s);
    float mean = sum / fmaxf(cnt, 1.f);
    float vals[4] = { sum, mean, mx, mn };
#pragma unroll
    for (int a = 0; a < 4; a++) {
        int m = a * D + c;
        out[b * 512 + (m & 3) * 128 + (m >> 2)] = vals[a];
    }
    if (c < 4) {
        int idx = NGRAPH * 4 * D + b * 4 + c;
        if (idx < out_size) out[idx] = 1.0f;
    }
    // ---- cleanup: re-zero rowptr for the next graph replay (replaces memset) ----
    int* rp = &g_rowptr[0][0];
    int total = 2 * (N_NODES + 1);
    for (int i = blockIdx.x * blockDim.x + threadIdx.x; i < total;
         i += gridDim.x * blockDim.x)
        rp[i] = 0;
}

// ---------------- launch ---------------------------------------------------------
extern "C" void kernel_launch(void* const* d_in, const int* in_sizes, int n_in,
                              void* d_out, int out_size) {
    const int*   x          = (const int*)d_in[0];
    const int*   e_pos      = (const int*)d_in[1];
    const int*   e_inv      = (const int*)d_in[2];
    const int*   batch      = (const int*)d_in[3];
    const float* type_emb   = (const float*)d_in[4];
    const float* output_emb = (const float*)d_in[5];
    const float* l1w        = (const float*)d_in[6];
    const float* l1b        = (const float*)d_in[7];
    const float* l2w        = (const float*)d_in[8];
    const float* l2b        = (const float*)d_in[9];
    float* out = (float*)d_out;

    float *hA, *hB;
    uint32_t *i0, *i1;
    int *rowptr, *rowS, *deg, *cursor, *csrsrc;
    __nv_bfloat16* wp;
    cudaGetSymbolAddress((void**)&hA, g_bufA);
    cudaGetSymbolAddress((void**)&hB, g_bufB);
    cudaGetSymbolAddress((void**)&i0, g_in0);
    cudaGetSymbolAddress((void**)&i1, g_in1);
    cudaGetSymbolAddress((void**)&rowptr, g_rowptr);
    cudaGetSymbolAddress((void**)&rowS, g_rowS);
    cudaGetSymbolAddress((void**)&deg, g_deg);
    cudaGetSymbolAddress((void**)&cursor, g_cursor);
    cudaGetSymbolAddress((void**)&csrsrc, g_csrsrc);
    cudaGetSymbolAddress((void**)&wp, g_wplanes);

    cudaFuncSetAttribute(gin_dual_kernel,
                         cudaFuncAttributeMaxDynamicSharedMemorySize, SM_TOTAL);

    // ---- CSR build + weight pre-split (rowptr pre-zeroed: static init +
    //      end-of-graph cleanup in pool_kernel) ----
    combo_kernel<<<HIST_BLKS + WSPLIT_BLKS, 256>>>(e_pos, e_inv, l1w, l2w, wp, rowptr);
    scan1_kernel<<<2 * NBLK, 256>>>(rowptr, rowS, deg, cursor);
    fill_kernel<<<(2 * N_EDGES + 255) / 256, 256>>>(e_pos, e_inv, cursor, csrsrc);

    const int gemm_grid = (N_NODES + 63) / 64;     // 1563
    const int gather_grid = (N_NODES * 32 + 255) / 256;

    // layer-0 aggregation in embedding space -> bf16 planes
    embed_gather2_kernel<<<gather_grid, 256>>>(x, type_emb, output_emb,
                                               rowS, deg, csrsrc, i0, i1);

    float* h  = hA;
    float* hn = hB;
    for (int l = 0; l < NUM_LAYER; l++) {
        if (l > 0)
            gather2_kernel<<<gather_grid, 256>>>(h, rowS, deg, csrsrc, i0, i1);

        const __nv_bfloat16* wpl = wp + (size_t)l * 2 * 4 * D * D;
        const float* b1p = l1b + (size_t)l * 2 * D;
        const float* b2p = l2b + (size_t)l * 2 * D;
        gin_dual_kernel<<<gemm_grid, 256, SM_TOTAL>>>(
            i0, i1, wpl, b1p, b2p, hn,
            /*relu_out=*/(l < NUM_LAYER - 1) ? 1 : 0);

        float* tmp = h; h = hn; hn = tmp;
    }

    pool_kernel<<<NGRAPH, D>>>(h, batch, out, out_size);
}